// round 6
// baseline (speedup 1.0000x reference)
#include <cuda_runtime.h>
#include <cuda_bf16.h>
#include <cstdint>

typedef unsigned int u32;
typedef unsigned long long u64;

#define C_IN   64
#define C_OUT  128
#define KK     27
#define HH     100000
#define TILE_H 128
#define TILE_O 64
#define NBLK   ((HH + TILE_H - 1) / TILE_H)
#define NTHR   256

// smem: 128B rows + SW128 XOR swizzle (conflict-free ldmatrix)
#define ST_AH  0
#define ST_AL  16384               // A: 128 rows x 128 B each half
#define ST_BH  32768               // B: 64 rows x 128 B each half
#define ST_BL  40960
#define STAGE  49152
#define NSTAGE 2
#define TILES_OFF 14336            // after sIdx (13824 B)
#define SMEM_BYTES (TILES_OFF + NSTAGE * STAGE)   // 112640

#define SWZ(o) ((o) ^ (((o) >> 3) & 0x70))

// ---------------- device scratch ----------------
__device__ __nv_bfloat16 g_xhi[(size_t)HH * C_IN];
__device__ __nv_bfloat16 g_xlo[(size_t)HH * C_IN];
__device__ __nv_bfloat16 g_whi[KK * C_OUT * C_IN];   // [k][o][c]
__device__ __nv_bfloat16 g_wlo[KK * C_OUT * C_IN];
__device__ int g_is64;

// ---------------- helpers ----------------
__device__ __forceinline__ u32 smem_u32(const void* p) {
    u32 a;
    asm("{ .reg .u64 t; cvta.to.shared.u64 t, %1; cvt.u32.u64 %0, t; }" : "=r"(a) : "l"(p));
    return a;
}
__device__ __forceinline__ void ldsm4(u32* r, u32 addr) {
    asm volatile("ldmatrix.sync.aligned.m8n8.x4.shared.b16 {%0,%1,%2,%3}, [%4];"
                 : "=r"(r[0]), "=r"(r[1]), "=r"(r[2]), "=r"(r[3]) : "r"(addr));
}
__device__ __forceinline__ void mma16816(float* d, const u32* a, const u32* b) {
    asm volatile("mma.sync.aligned.m16n8k16.row.col.f32.bf16.bf16.f32 "
                 "{%0,%1,%2,%3}, {%4,%5,%6,%7}, {%8,%9}, {%0,%1,%2,%3};"
                 : "+f"(d[0]), "+f"(d[1]), "+f"(d[2]), "+f"(d[3])
                 : "r"(a[0]), "r"(a[1]), "r"(a[2]), "r"(a[3]), "r"(b[0]), "r"(b[1]));
}
#define CP16(dst, src) \
    asm volatile("cp.async.cg.shared.global [%0], [%1], 16;" ::"r"(dst), "l"(src) : "memory")
#define CP16Z(dst, src, sz) \
    asm volatile("cp.async.cg.shared.global [%0], [%1], 16, %2;" ::"r"(dst), "l"(src), "r"(sz) : "memory")
#define CP_COMMIT() asm volatile("cp.async.commit_group;" ::: "memory")
#define CP_WAIT1()  asm volatile("cp.async.wait_group 1;" ::: "memory")

// ---------------- prep kernels ----------------
__global__ void detect_dtype(const long long* __restrict__ n64) {
    if (threadIdx.x == 0 && blockIdx.x == 0) {
        int ok = 1;
        for (int i = 0; i < 256; i++) {
            long long v = n64[i];
            if (v < -(long long)HH || v >= (long long)HH) { ok = 0; break; }
        }
        g_is64 = ok;
    }
}

__global__ void split_x(const float* __restrict__ x) {
    __shared__ float tile[32][33];
    const int hb = blockIdx.x * 32, cb = blockIdx.y * 32;
    const int tx = threadIdx.x, ty = threadIdx.y;
#pragma unroll
    for (int i = 0; i < 32; i += 8) {
        int h = hb + tx;
        tile[ty + i][tx] = (h < HH) ? x[(size_t)(cb + ty + i) * HH + h] : 0.f;
    }
    __syncthreads();
#pragma unroll
    for (int i = 0; i < 32; i += 8) {
        int h = hb + ty + i, c = cb + tx;
        if (h < HH) {
            float v = tile[tx][ty + i];
            __nv_bfloat16 hi = __float2bfloat16(v);
            float r = v - __bfloat162float(hi);
            g_xhi[(size_t)h * C_IN + c] = hi;
            g_xlo[(size_t)h * C_IN + c] = __float2bfloat16(r);
        }
    }
}

__global__ void split_w(const float* __restrict__ w) {
    int idx = blockIdx.x * blockDim.x + threadIdx.x;
    if (idx >= KK * C_OUT * C_IN) return;
    int k = idx / (C_OUT * C_IN);
    int rem = idx % (C_OUT * C_IN);
    int o = rem / C_IN, c = rem % C_IN;
    float v = w[(size_t)o * (C_IN * KK) + c * KK + k];
    __nv_bfloat16 hi = __float2bfloat16(v);
    float r = v - __bfloat162float(hi);
    g_whi[idx] = hi;
    g_wlo[idx] = __float2bfloat16(r);
}

// ---------------- main kernel ----------------
__global__ __launch_bounds__(NTHR, 2)
void conv_mma(const void* __restrict__ neigh_raw, float* __restrict__ out) {
    extern __shared__ char smem[];
    const u32 sbase = smem_u32(smem);
    int* sIdx = (int*)smem;
    const u32 tiles = sbase + TILES_OFF;

    const int tid = threadIdx.x;
    const int lid = tid & 31, wid = tid >> 5;    // 8 warps
    const int wr = wid & 3, wc = wid >> 2;       // warp grid 4(h) x 2(o)
    const int hb = blockIdx.x * TILE_H;
    const int ob = blockIdx.y * TILE_O;          // o-half

    // ---- stage neighbor indices ----
    {
        const int is64 = g_is64;
        const long long* n64 = (const long long*)neigh_raw;
        const int* n32 = (const int*)neigh_raw;
        for (int j = tid; j < TILE_H * KK; j += NTHR) {
            int hl = j / KK;
            int n = -1;
            if (hb + hl < HH) {
                size_t gi = (size_t)(hb + hl) * KK + (j % KK);
                long long v = is64 ? n64[gi] : (long long)n32[gi];
                if (v >= 0 && v < HH) n = (int)v;
            }
            sIdx[j] = n;
        }
    }
    __syncthreads();

    // ---- per-thread load roles ----
    const int ar   = tid >> 1;                 // gather row 0..127
    const int asel = tid & 1;                  // 0 = hi, 1 = lo
    const __nv_bfloat16* axsrc = asel ? g_xlo : g_xhi;
    const u32 atile = asel ? ST_AL : ST_AH;

    // ---- ldmatrix lane address components ----
    const u32 a_ro = (u32)(lid & 15);
    const u32 a_co = (u32)(lid >> 4);
    const u32 b_ro = (u32)((lid & 7) + ((lid >> 4) << 3));
    const u32 b_co = (u32)((lid >> 3) & 1);
    const u32 a_row = (u32)(wr * 32) + a_ro;
    const u32 b_row = (u32)(wc * 32) + b_ro;

    float acc[2][4][4];
#pragma unroll
    for (int mf = 0; mf < 2; mf++)
#pragma unroll
        for (int nf = 0; nf < 4; nf++)
#pragma unroll
            for (int r = 0; r < 4; r++) acc[mf][nf][r] = 0.f;

    // ---- async load issuer for tap k into stage stg ----
    auto issue = [&](int k, int stg) {
        const u32 st = tiles + stg * STAGE;
        // A: this thread's gather row (hi or lo), 8 x 16B, swizzled
        int n = sIdx[ar * KK + k];
        const char* src = (const char*)(axsrc + (n < 0 ? 0 : (size_t)n * C_IN));
        u32 sz = (n < 0) ? 0u : 16u;
        u32 rowoff = (u32)ar * 128;
#pragma unroll
        for (int j = 0; j < 8; j++)
            CP16Z(st + atile + SWZ(rowoff + j * 16), src + j * 16, sz);
        // B: this o-half's weights hi+lo, 2 chunks each
        const __nv_bfloat16* bh0 = g_whi + (size_t)k * (C_OUT * C_IN) + (size_t)ob * C_IN;
        const __nv_bfloat16* bl0 = g_wlo + (size_t)k * (C_OUT * C_IN) + (size_t)ob * C_IN;
#pragma unroll
        for (int i = 0; i < 2; i++) {
            int cc = tid + i * NTHR;           // 0..511 16B chunks
            u32 d = SWZ((u32)cc * 16);
            CP16(st + ST_BH + d, (const char*)bh0 + cc * 16);
            CP16(st + ST_BL + d, (const char*)bl0 + cc * 16);
        }
    };

    issue(0, 0); CP_COMMIT();
    issue(1, 1); CP_COMMIT();

    int stg = 0;
    for (int k = 0; k < KK; k++) {
        CP_WAIT1();
        __syncthreads();

        const u32 st = tiles + stg * STAGE;
#pragma unroll
        for (int ks = 0; ks < 4; ks++) {
            u32 ah[2][4], al[2][4], bh[2][4], bl[2][4];
#pragma unroll
            for (int mf = 0; mf < 2; mf++) {
                u32 off = (a_row + mf * 16) * 128 + (u32)(ks * 32) + a_co * 16;
                u32 ad = st + SWZ(off);
                ldsm4(ah[mf], ad);
                ldsm4(al[mf], ad + (ST_AL - ST_AH));
            }
#pragma unroll
            for (int g = 0; g < 2; g++) {
                u32 off = (b_row + g * 16) * 128 + (u32)(ks * 32) + b_co * 16;
                u32 bd = st + ST_BH + SWZ(off);
                ldsm4(bh[g], bd);
                ldsm4(bl[g], bd + (ST_BL - ST_BH));
            }
            // term-major order: 8 independent MMAs between same-acc touches
#pragma unroll
            for (int mf = 0; mf < 2; mf++)
#pragma unroll
                for (int g = 0; g < 2; g++) {
                    mma16816(acc[mf][2 * g],     ah[mf], &bh[g][0]);
                    mma16816(acc[mf][2 * g + 1], ah[mf], &bh[g][2]);
                }
#pragma unroll
            for (int mf = 0; mf < 2; mf++)
#pragma unroll
                for (int g = 0; g < 2; g++) {
                    mma16816(acc[mf][2 * g],     al[mf], &bh[g][0]);
                    mma16816(acc[mf][2 * g + 1], al[mf], &bh[g][2]);
                }
#pragma unroll
            for (int mf = 0; mf < 2; mf++)
#pragma unroll
                for (int g = 0; g < 2; g++) {
                    mma16816(acc[mf][2 * g],     ah[mf], &bl[g][0]);
                    mma16816(acc[mf][2 * g + 1], ah[mf], &bl[g][2]);
                }
        }
        __syncthreads();
        if (k + 2 < KK) issue(k + 2, stg);
        CP_COMMIT();
        stg ^= 1;
    }

    // ---- epilogue: stage through smem (pitch 132 f32), coalesced f4 stores ----
    float* sC = (float*)(smem + TILES_OFF);
#pragma unroll
    for (int mf = 0; mf < 2; mf++)
#pragma unroll
        for (int nf = 0; nf < 4; nf++)
#pragma unroll
            for (int r = 0; r < 4; r++) {
                int m = wr * 32 + mf * 16 + (lid >> 2) + ((r >> 1) << 3);
                int n = wc * 32 + nf * 8 + ((lid & 3) << 1) + (r & 1);
                sC[n * 132 + m] = fmaxf(acc[mf][nf][r], 0.f);
            }
    __syncthreads();
#pragma unroll
    for (int it = 0; it < 8; it++) {
        int idx = it * NTHR + tid;               // 2048 float4 stores
        int o = idx >> 5, hq = idx & 31;
        int h = hb + hq * 4;
        if (h < HH) {
            float4 v = *(const float4*)(sC + o * 132 + hq * 4);
            *(float4*)(out + (size_t)(ob + o) * HH + h) = v;
        }
    }
}

// ---------------- launch ----------------
extern "C" void kernel_launch(void* const* d_in, const int* in_sizes, int n_in,
                              void* d_out, int out_size) {
    const float* x = (const float*)d_in[0];
    const void* neigh = d_in[1];
    const float* w = (const float*)d_in[2];
    float* out = (float*)d_out;

    cudaFuncSetAttribute(conv_mma, cudaFuncAttributeMaxDynamicSharedMemorySize, SMEM_BYTES);

    detect_dtype<<<1, 32>>>((const long long*)neigh);
    split_x<<<dim3((HH + 31) / 32, C_IN / 32), dim3(32, 8)>>>(x);
    split_w<<<(KK * C_OUT * C_IN + 255) / 256, 256>>>(w);
    conv_mma<<<dim3(NBLK, C_OUT / TILE_O), NTHR, SMEM_BYTES>>>(neigh, out);
}

// round 7
// speedup vs baseline: 1.2662x; 1.2662x over previous
#include <cuda_runtime.h>
#include <cuda_bf16.h>
#include <cstdint>

typedef unsigned int u32;
typedef unsigned long long u64;

#define C_IN   64
#define C_OUT  128
#define KK     27
#define HH     100000
#define TILE_H 128
#define NBLK   ((HH + TILE_H - 1) / TILE_H)
#define NTHR   512

// smem: 128B rows + SW128 XOR swizzle (conflict-free ldmatrix)
#define ST_AH  0
#define ST_AL  16384
#define ST_BH  32768
#define ST_BL  49152
#define STAGE  65536
#define NSTAGE 3
#define TILES_OFF 14336            // after sIdx (13824 B)
#define SMEM_BYTES (TILES_OFF + NSTAGE * STAGE)   // 210944

#define SWZ(o) ((o) ^ (((o) >> 3) & 0x70))

// ---------------- device scratch ----------------
__device__ __nv_bfloat16 g_xhi[(size_t)HH * C_IN];
__device__ __nv_bfloat16 g_xlo[(size_t)HH * C_IN];
__device__ __nv_bfloat16 g_whi[KK * C_OUT * C_IN];   // [k][o][c]
__device__ __nv_bfloat16 g_wlo[KK * C_OUT * C_IN];
__device__ int g_is64;

// ---------------- helpers ----------------
__device__ __forceinline__ u32 smem_u32(const void* p) {
    u32 a;
    asm("{ .reg .u64 t; cvta.to.shared.u64 t, %1; cvt.u32.u64 %0, t; }" : "=r"(a) : "l"(p));
    return a;
}
__device__ __forceinline__ void ldsm4(u32* r, u32 addr) {
    asm volatile("ldmatrix.sync.aligned.m8n8.x4.shared.b16 {%0,%1,%2,%3}, [%4];"
                 : "=r"(r[0]), "=r"(r[1]), "=r"(r[2]), "=r"(r[3]) : "r"(addr));
}
__device__ __forceinline__ void mma16816(float* d, const u32* a, const u32* b) {
    asm volatile("mma.sync.aligned.m16n8k16.row.col.f32.bf16.bf16.f32 "
                 "{%0,%1,%2,%3}, {%4,%5,%6,%7}, {%8,%9}, {%0,%1,%2,%3};"
                 : "+f"(d[0]), "+f"(d[1]), "+f"(d[2]), "+f"(d[3])
                 : "r"(a[0]), "r"(a[1]), "r"(a[2]), "r"(a[3]), "r"(b[0]), "r"(b[1]));
}
#define CP16(dst, src) \
    asm volatile("cp.async.cg.shared.global [%0], [%1], 16;" ::"r"(dst), "l"(src) : "memory")
#define CP16Z(dst, src, sz) \
    asm volatile("cp.async.cg.shared.global [%0], [%1], 16, %2;" ::"r"(dst), "l"(src), "r"(sz) : "memory")
#define CP_COMMIT() asm volatile("cp.async.commit_group;" ::: "memory")
#define CP_WAIT1()  asm volatile("cp.async.wait_group 1;" ::: "memory")

// ---------------- prep kernels ----------------
__global__ void detect_dtype(const long long* __restrict__ n64) {
    if (threadIdx.x == 0 && blockIdx.x == 0) {
        int ok = 1;
        for (int i = 0; i < 256; i++) {
            long long v = n64[i];
            if (v < -(long long)HH || v >= (long long)HH) { ok = 0; break; }
        }
        g_is64 = ok;
    }
}

__global__ void split_x(const float* __restrict__ x) {
    __shared__ float tile[32][33];
    const int hb = blockIdx.x * 32, cb = blockIdx.y * 32;
    const int tx = threadIdx.x, ty = threadIdx.y;
#pragma unroll
    for (int i = 0; i < 32; i += 8) {
        int h = hb + tx;
        tile[ty + i][tx] = (h < HH) ? x[(size_t)(cb + ty + i) * HH + h] : 0.f;
    }
    __syncthreads();
#pragma unroll
    for (int i = 0; i < 32; i += 8) {
        int h = hb + ty + i, c = cb + tx;
        if (h < HH) {
            float v = tile[tx][ty + i];
            __nv_bfloat16 hi = __float2bfloat16(v);
            float r = v - __bfloat162float(hi);
            g_xhi[(size_t)h * C_IN + c] = hi;
            g_xlo[(size_t)h * C_IN + c] = __float2bfloat16(r);
        }
    }
}

__global__ void split_w(const float* __restrict__ w) {
    int idx = blockIdx.x * blockDim.x + threadIdx.x;
    if (idx >= KK * C_OUT * C_IN) return;
    int k = idx / (C_OUT * C_IN);
    int rem = idx % (C_OUT * C_IN);
    int o = rem / C_IN, c = rem % C_IN;
    float v = w[(size_t)o * (C_IN * KK) + c * KK + k];
    __nv_bfloat16 hi = __float2bfloat16(v);
    float r = v - __bfloat162float(hi);
    g_whi[idx] = hi;
    g_wlo[idx] = __float2bfloat16(r);
}

// ---------------- main kernel ----------------
__global__ __launch_bounds__(NTHR, 1)
void conv_mma(const void* __restrict__ neigh_raw, float* __restrict__ out) {
    extern __shared__ char smem[];
    const u32 sbase = smem_u32(smem);
    int* sIdx = (int*)smem;
    const u32 tiles = sbase + TILES_OFF;

    const int tid = threadIdx.x;
    const int lid = tid & 31, wid = tid >> 5;    // 16 warps
    const int wr = wid & 3, wc = wid >> 2;       // warp grid 4(h) x 4(o)
    const int hb = blockIdx.x * TILE_H;

    // ---- stage neighbor indices ----
    {
        const int is64 = g_is64;
        const long long* n64 = (const long long*)neigh_raw;
        const int* n32 = (const int*)neigh_raw;
        for (int j = tid; j < TILE_H * KK; j += NTHR) {
            int hl = j / KK;
            int n = -1;
            if (hb + hl < HH) {
                size_t gi = (size_t)(hb + hl) * KK + (j % KK);
                long long v = is64 ? n64[gi] : (long long)n32[gi];
                if (v >= 0 && v < HH) n = (int)v;
            }
            sIdx[j] = n;
        }
    }
    __syncthreads();

    // ---- per-thread load roles: A = (row, half, 4-chunk group) ----
    const int ar   = tid >> 2;                 // 0..127
    const int asel = (tid >> 1) & 1;           // 0 = hi, 1 = lo
    const int jgrp = (tid & 1) * 4;            // chunk group
    const __nv_bfloat16* axsrc = asel ? g_xlo : g_xhi;
    const u32 atile = asel ? ST_AL : ST_AH;

    // ---- ldmatrix address precompute (SWZ(row*128+t) = row*128 + (t ^ ((row&7)*16))) ----
    const u32 a_ro = (u32)(lid & 15);
    const u32 a_co = (u32)(lid >> 4);
    const u32 b_ro = (u32)((lid & 7) + ((lid >> 4) << 3));
    const u32 b_co = (u32)((lid >> 3) & 1);
    const u32 a_row = (u32)(wr * 32) + a_ro;
    const u32 b_row = (u32)(wc * 32) + b_ro;
    const u32 axor = (a_row & 7) * 16;
    const u32 bxor = (b_row & 7) * 16;
    u32 arow0 = a_row * 128, arow1 = (a_row + 16) * 128;
    u32 brow0 = b_row * 128, brow1 = (b_row + 16) * 128;
    u32 koffA[4], koffB[4];
#pragma unroll
    for (int ks = 0; ks < 4; ks++) {
        koffA[ks] = ((u32)(ks * 32) + a_co * 16) ^ axor;
        koffB[ks] = ((u32)(ks * 32) + b_co * 16) ^ bxor;
    }

    float acc[2][4][4];
#pragma unroll
    for (int mf = 0; mf < 2; mf++)
#pragma unroll
        for (int nf = 0; nf < 4; nf++)
#pragma unroll
            for (int r = 0; r < 4; r++) acc[mf][nf][r] = 0.f;

    // ---- async load issuer for tap k into stage stg ----
    auto issue = [&](int k, int stg) {
        const u32 st = tiles + stg * STAGE;
        int n = sIdx[ar * KK + k];
        const char* src = (const char*)(axsrc + (n < 0 ? 0 : (size_t)n * C_IN)) + jgrp * 16;
        u32 sz = (n < 0) ? 0u : 16u;
        u32 rowoff = (u32)ar * 128 + (u32)jgrp * 16;
#pragma unroll
        for (int j = 0; j < 4; j++)
            CP16Z(st + atile + SWZ(rowoff + j * 16), src + j * 16, sz);
        const char* bhs = (const char*)(g_whi + (size_t)k * (C_OUT * C_IN));
        const char* bls = (const char*)(g_wlo + (size_t)k * (C_OUT * C_IN));
#pragma unroll
        for (int i = 0; i < 2; i++) {
            int cc = tid + i * NTHR;
            u32 d = SWZ((u32)cc * 16);
            CP16(st + ST_BH + d, bhs + cc * 16);
            CP16(st + ST_BL + d, bls + cc * 16);
        }
    };

    issue(0, 0); CP_COMMIT();
    issue(1, 1); CP_COMMIT();

    // fragment double buffers (al single-buffered)
    u32 ah[2][2][4], bh[2][2][4], bl[2][2][4], al[2][4];

    int stg = 0, stgW = 2;                    // write target = (k+2)%3
    for (int k = 0; k < KK; k++) {
        CP_WAIT1();
        __syncthreads();

        if (k + 2 < KK) issue(k + 2, stgW);
        CP_COMMIT();

        const u32 st  = tiles + stg * STAGE;
        const u32 stB = st + ST_BH;

        // prologue: ks=0 fragments into buf 0
        ldsm4(ah[0][0], st + arow0 + koffA[0]);
        ldsm4(ah[0][1], st + arow1 + koffA[0]);
        ldsm4(bh[0][0], stB + brow0 + koffB[0]);
        ldsm4(bh[0][1], stB + brow1 + koffB[0]);
        ldsm4(bl[0][0], stB + 16384 + brow0 + koffB[0]);
        ldsm4(bl[0][1], stB + 16384 + brow1 + koffB[0]);

#pragma unroll
        for (int ks = 0; ks < 4; ks++) {
            const int cur = ks & 1, nxt = cur ^ 1;
            // group 1: ah . bh   (8 independent MMAs)
#pragma unroll
            for (int mf = 0; mf < 2; mf++)
#pragma unroll
                for (int g = 0; g < 2; g++) {
                    mma16816(acc[mf][2 * g],     ah[cur][mf], &bh[cur][g][0]);
                    mma16816(acc[mf][2 * g + 1], ah[cur][mf], &bh[cur][g][2]);
                }
            // load al for this ks
            ldsm4(al[0], st + 16384 + arow0 + koffA[ks]);
            ldsm4(al[1], st + 16384 + arow1 + koffA[ks]);
            // group 2: ah . bl
#pragma unroll
            for (int mf = 0; mf < 2; mf++)
#pragma unroll
                for (int g = 0; g < 2; g++) {
                    mma16816(acc[mf][2 * g],     ah[cur][mf], &bl[cur][g][0]);
                    mma16816(acc[mf][2 * g + 1], ah[cur][mf], &bl[cur][g][2]);
                }
            // prefetch next ks fragments
            if (ks < 3) {
                ldsm4(ah[nxt][0], st + arow0 + koffA[ks + 1]);
                ldsm4(ah[nxt][1], st + arow1 + koffA[ks + 1]);
                ldsm4(bh[nxt][0], stB + brow0 + koffB[ks + 1]);
                ldsm4(bh[nxt][1], stB + brow1 + koffB[ks + 1]);
                ldsm4(bl[nxt][0], stB + 16384 + brow0 + koffB[ks + 1]);
                ldsm4(bl[nxt][1], stB + 16384 + brow1 + koffB[ks + 1]);
            }
            // group 3: al . bh
#pragma unroll
            for (int mf = 0; mf < 2; mf++)
#pragma unroll
                for (int g = 0; g < 2; g++) {
                    mma16816(acc[mf][2 * g],     al[mf], &bh[cur][g][0]);
                    mma16816(acc[mf][2 * g + 1], al[mf], &bh[cur][g][2]);
                }
        }

        stg  = (stg == NSTAGE - 1) ? 0 : stg + 1;
        stgW = (stgW == NSTAGE - 1) ? 0 : stgW + 1;
    }

    __syncthreads();
    // ---- epilogue: stage through smem (pitch 132 f32), coalesced f4 stores ----
    float* sC = (float*)(smem + TILES_OFF);
#pragma unroll
    for (int mf = 0; mf < 2; mf++)
#pragma unroll
        for (int nf = 0; nf < 4; nf++)
#pragma unroll
            for (int r = 0; r < 4; r++) {
                int m = wr * 32 + mf * 16 + (lid >> 2) + ((r >> 1) << 3);
                int n = wc * 32 + nf * 8 + ((lid & 3) << 1) + (r & 1);
                sC[n * 132 + m] = fmaxf(acc[mf][nf][r], 0.f);
            }
    __syncthreads();
#pragma unroll
    for (int it = 0; it < 8; it++) {
        int idx = it * NTHR + tid;
        int o = idx >> 5, hq = idx & 31;
        int h = hb + hq * 4;
        if (h < HH) {
            float4 v = *(const float4*)(sC + o * 132 + hq * 4);
            *(float4*)(out + (size_t)o * HH + h) = v;
        }
    }
}

// ---------------- launch ----------------
extern "C" void kernel_launch(void* const* d_in, const int* in_sizes, int n_in,
                              void* d_out, int out_size) {
    const float* x = (const float*)d_in[0];
    const void* neigh = d_in[1];
    const float* w = (const float*)d_in[2];
    float* out = (float*)d_out;

    cudaFuncSetAttribute(conv_mma, cudaFuncAttributeMaxDynamicSharedMemorySize, SMEM_BYTES);

    detect_dtype<<<1, 32>>>((const long long*)neigh);
    split_x<<<dim3((HH + 31) / 32, C_IN / 32), dim3(32, 8)>>>(x);
    split_w<<<(KK * C_OUT * C_IN + 255) / 256, 256>>>(w);
    conv_mma<<<NBLK, NTHR, SMEM_BYTES>>>(neigh, out);
}